// round 16
// baseline (speedup 1.0000x reference)
#include <cuda_runtime.h>
#include <cuda_bf16.h>
#include <cuda_fp16.h>
#include <math.h>
#include <stdint.h>

#define DIMC 1024
#define HD 64
#define NH 16
#define BATCH 2
#define NQ 1024
#define MKV 2048
#define ATT_SCALE 0.125f
#define SC2 0.18033688f   // ATT_SCALE * log2(e)

// ---------------------------------------------------------------------------
// Scratch (pure fp16)
// ---------------------------------------------------------------------------
__device__ __align__(16) __half gb_xh[(size_t)BATCH * NQ * DIMC];
__device__ __align__(16) __half gb_ch[(size_t)BATCH * MKV * DIMC];
__device__ __align__(16) __half gb_wqh[(size_t)DIMC * DIMC];
__device__ __align__(16) __half gb_wkvh[(size_t)2 * DIMC * DIMC];
__device__ __align__(16) __half gb_woh[(size_t)DIMC * DIMC];
__device__ __align__(16) __half gb_aoh[(size_t)BATCH * NQ * DIMC];
__device__ __align__(16) __half g_qh[(size_t)BATCH * NH * NQ * HD];
__device__ __align__(16) __half g_kh[(size_t)BATCH * NH * MKV * HD];
__device__ __align__(16) __half g_vh[(size_t)BATCH * NH * MKV * HD];
__device__ __align__(16) unsigned int g_mw[(size_t)BATCH * NQ * MKV / 32];

// ---------------------------------------------------------------------------
// PTX helpers
// ---------------------------------------------------------------------------
__device__ __forceinline__ uint32_t smem_u32(const void* p) {
    uint32_t a;
    asm("{ .reg .u64 t; cvta.to.shared.u64 t, %1; cvt.u32.u64 %0, t; }"
        : "=r"(a) : "l"(p));
    return a;
}

#define CP_ASYNC16(dst, src) \
    asm volatile("cp.async.cg.shared.global [%0], [%1], 16;" \
                 :: "r"(dst), "l"(src) : "memory")
#define CP_ASYNC8(dst, src) \
    asm volatile("cp.async.ca.shared.global [%0], [%1], 8;" \
                 :: "r"(dst), "l"(src) : "memory")
#define CP_COMMIT() asm volatile("cp.async.commit_group;" ::: "memory")
#define CP_WAIT4()  asm volatile("cp.async.wait_group 4;" ::: "memory")
#define CP_WAIT2()  asm volatile("cp.async.wait_group 2;" ::: "memory")
#define CP_WAIT1()  asm volatile("cp.async.wait_group 1;" ::: "memory")
#define CP_WAIT0()  asm volatile("cp.async.wait_group 0;" ::: "memory")

__device__ __forceinline__ void ldsm_x4(uint32_t* r, uint32_t addr) {
    asm volatile("ldmatrix.sync.aligned.m8n8.x4.shared.b16 {%0,%1,%2,%3}, [%4];"
                 : "=r"(r[0]), "=r"(r[1]), "=r"(r[2]), "=r"(r[3]) : "r"(addr));
}
__device__ __forceinline__ void ldsm_x4_t(uint32_t* r, uint32_t addr) {
    asm volatile("ldmatrix.sync.aligned.m8n8.x4.trans.shared.b16 {%0,%1,%2,%3}, [%4];"
                 : "=r"(r[0]), "=r"(r[1]), "=r"(r[2]), "=r"(r[3]) : "r"(addr));
}
__device__ __forceinline__ void mma_f16(float* c, const uint32_t* a, const uint32_t* b) {
    asm volatile(
        "mma.sync.aligned.m16n8k16.row.col.f32.f16.f16.f32 "
        "{%0,%1,%2,%3}, {%4,%5,%6,%7}, {%8,%9}, {%0,%1,%2,%3};"
        : "+f"(c[0]), "+f"(c[1]), "+f"(c[2]), "+f"(c[3])
        : "r"(a[0]), "r"(a[1]), "r"(a[2]), "r"(a[3]), "r"(b[0]), "r"(b[1]));
}

__device__ __forceinline__ uint32_t exp2pk(float a, float b) {
    uint32_t h;
    asm("cvt.rn.f16x2.f32 %0, %1, %2;" : "=r"(h) : "f"(b), "f"(a));
    asm("ex2.approx.f16x2 %0, %0;" : "+r"(h));
    return h;
}
__device__ __forceinline__ void store_h2(__half* H, size_t idx, float v0, float v1) {
    *(__half2*)(H + idx) = __halves2half2(__float2half_rn(v0), __float2half_rn(v1));
}

// ---------------------------------------------------------------------------
// Prep: fp32 -> fp16 convert only (mask packing moved into proj grid)
// ---------------------------------------------------------------------------
#define NXQ ((BATCH * NQ * DIMC) / 4)
#define NCTXQ ((BATCH * MKV * DIMC) / 4)
#define NWQQ ((DIMC * DIMC) / 4)
#define NWKVQ ((2 * DIMC * DIMC) / 4)
#define NWOQ ((DIMC * DIMC) / 4)
#define NCONVQ (NXQ + NCTXQ + NWQQ + NWKVQ + NWOQ)
#define NMASKE (BATCH * NQ * MKV)

__global__ void prep_k(const float* __restrict__ x, const float* __restrict__ ctx,
                       const float* __restrict__ Wq, const float* __restrict__ Wkv,
                       const float* __restrict__ Wo)
{
    int i = blockIdx.x * blockDim.x + threadIdx.x;
    const int q0 = NXQ, q1 = q0 + NCTXQ, q2 = q1 + NWQQ, q3 = q2 + NWKVQ, q4 = q3 + NWOQ;
    if (i >= q4) return;

    const float* src; __half* H; int off = i;
    if (i < q0)      { src = x;   H = gb_xh; }
    else if (i < q1) { src = ctx; H = gb_ch;   off -= q0; }
    else if (i < q2) { src = Wq;  H = gb_wqh;  off -= q1; }
    else if (i < q3) { src = Wkv; H = gb_wkvh; off -= q2; }
    else             { src = Wo;  H = gb_woh;  off -= q3; }
    float4 v = ((const float4*)src)[off];
    __half2 hp0 = __halves2half2(__float2half_rn(v.x), __float2half_rn(v.y));
    __half2 hp1 = __halves2half2(__float2half_rn(v.z), __float2half_rn(v.w));
    uint2 hp;
    hp.x = *(uint32_t*)&hp0; hp.y = *(uint32_t*)&hp1;
    ((uint2*)H)[off] = hp;
}

// ---------------------------------------------------------------------------
// Shared GEMM tile constants: BK=64, 3-stage
// ---------------------------------------------------------------------------
#define BK 64
#define GK 1024
#define GNT (GK / BK)
#define ROWB 144
#define TILEB (128 * ROWB)

// ============ proj mainloop: 256 threads, 3-stage, 1-term ==================
#define PROJ_STAGEB (2 * TILEB)
#define GEMM2_SMEM (3 * PROJ_STAGEB)

__device__ __forceinline__ void gemm_mainloop2(
    uint32_t sb, int tid,
    const __half* __restrict__ A, const __half* __restrict__ B,
    float acc[4][4][4])
{
    const int wid = tid >> 5, lane = tid & 31;
    const int wm = wid & 1;
    const int wn = wid >> 1;
    const __half* srcs[2] = { A, B };

    auto load_stage = [&](int t, int stage) {
        const uint32_t base = sb + stage * PROJ_STAGEB;
#pragma unroll
        for (int m = 0; m < 2; m++) {
            const __half* src = srcs[m] + (size_t)t * BK;
#pragma unroll
            for (int rep = 0; rep < 4; rep++) {
                int f = tid + rep * 256;
                int row = f >> 3;
                int ch = f & 7;
                CP_ASYNC16(base + m * TILEB + row * ROWB + ch * 16,
                           src + (size_t)row * GK + ch * 8);
            }
        }
        CP_COMMIT();
    };

    load_stage(0, 0);
    load_stage(1, 1);

    const int a_row = wm * 64 + (lane & 7) + 8 * ((lane >> 3) & 1);
    const int a_kof = 8 * (lane >> 4);
    const int b_row = wn * 32 + (lane & 7) + 8 * (lane >> 4);
    const int b_kof = 8 * ((lane >> 3) & 1);

    for (int t = 0; t < GNT; t++) {
        if (t + 1 < GNT) CP_WAIT1(); else CP_WAIT0();
        __syncthreads();
        if (t + 2 < GNT) load_stage(t + 2, (t + 2) % 3);

        const uint32_t sA = sb + (t % 3) * PROJ_STAGEB;
        const uint32_t sB = sA + TILEB;

#pragma unroll
        for (int kk = 0; kk < BK; kk += 16) {
            uint32_t a_f[4][4];
#pragma unroll
            for (int mt = 0; mt < 4; mt++) {
                uint32_t off = (uint32_t)(a_row + mt * 16) * ROWB + (kk + a_kof) * 2;
                ldsm_x4(a_f[mt], sA + off);
            }
            uint32_t b_f[8];
#pragma unroll
            for (int np = 0; np < 2; np++) {
                uint32_t off = (uint32_t)(b_row + np * 16) * ROWB + (kk + b_kof) * 2;
                ldsm_x4(b_f + np * 4, sB + off);
            }
#pragma unroll
            for (int mt = 0; mt < 4; mt++)
#pragma unroll
                for (int nt = 0; nt < 4; nt++)
                    mma_f16(acc[mt][nt], a_f[mt], b_f + nt * 2);
        }
    }
}

// ============ out mainloop: 512 threads, 3-stage, 1-term ===================
#define OUT_STAGEB (2 * TILEB)
#define GEMM4_SMEM (3 * OUT_STAGEB)

__device__ __forceinline__ void gemm_mainloop4(
    uint32_t sb, int tid,
    const __half* __restrict__ A, const __half* __restrict__ B,
    float acc[2][4][4])
{
    const int wid = tid >> 5, lane = tid & 31;
    const int wm = wid & 3;
    const int wn = wid >> 2;
    const __half* srcs[2] = { A, B };

    auto load_stage = [&](int t, int stage) {
        const uint32_t base = sb + stage * OUT_STAGEB;
#pragma unroll
        for (int m = 0; m < 2; m++) {
            const __half* src = srcs[m] + (size_t)t * BK;
#pragma unroll
            for (int rep = 0; rep < 2; rep++) {
                int f = tid + rep * 512;
                int row = f >> 3;
                int ch = f & 7;
                CP_ASYNC16(base + m * TILEB + row * ROWB + ch * 16,
                           src + (size_t)row * GK + ch * 8);
            }
        }
        CP_COMMIT();
    };

    load_stage(0, 0);
    load_stage(1, 1);

    const int a_rowb = wm * 32 + (lane & 7) + 8 * ((lane >> 3) & 1);
    const int a_kof = 8 * (lane >> 4);
    const int b_rowb = wn * 32 + (lane & 7) + 8 * (lane >> 4);
    const int b_kof = 8 * ((lane >> 3) & 1);

    for (int t = 0; t < GNT; t++) {
        if (t + 1 < GNT) CP_WAIT1(); else CP_WAIT0();
        __syncthreads();
        if (t + 2 < GNT) load_stage(t + 2, (t + 2) % 3);

        const uint32_t sA = sb + (t % 3) * OUT_STAGEB;
        const uint32_t sB = sA + TILEB;

#pragma unroll
        for (int kk = 0; kk < BK; kk += 16) {
            uint32_t a_f[2][4];
#pragma unroll
            for (int mt = 0; mt < 2; mt++) {
                uint32_t off = (uint32_t)(a_rowb + mt * 16) * ROWB + (kk + a_kof) * 2;
                ldsm_x4(a_f[mt], sA + off);
            }
            uint32_t b_f[8];
#pragma unroll
            for (int np = 0; np < 2; np++) {
                uint32_t off = (uint32_t)(b_rowb + np * 16) * ROWB + (kk + b_kof) * 2;
                ldsm_x4(b_f + np * 4, sB + off);
            }
#pragma unroll
            for (int mt = 0; mt < 2; mt++)
#pragma unroll
                for (int nt = 0; nt < 4; nt++)
                    mma_f16(acc[mt][nt], a_f[mt], b_f + nt * 2);
        }
    }
}

// ---------------------------------------------------------------------------
// Merged Q + KV projection + mask-pack CTAs (bid >= 640)
// ---------------------------------------------------------------------------
#define PROJ_GRID 672
#define MASK_CTAS 32
#define MASK_PER_CTA (NMASKE / MASK_CTAS)   // 131072

__global__ __launch_bounds__(256, 2) void proj_tc(const float* __restrict__ b_kv,
                                                  const unsigned int* __restrict__ mask)
{
    const int tid = threadIdx.x;
    const int bid = blockIdx.x;

    if (bid >= 640) {
        // mask packing
        int mb = bid - 640;
        const int base = mb * MASK_PER_CTA;
        for (int k = 0; k < MASK_PER_CTA; k += 256) {
            int j = base + k + tid;
            unsigned int v = mask[j];
            unsigned int bits = __ballot_sync(0xffffffffu, v != 0u);
            if ((tid & 31) == 0) g_mw[j >> 5] = bits;
        }
        return;
    }

    extern __shared__ char smem[];
    const uint32_t sb = smem_u32(smem);
    const int wid = tid >> 5, lane = tid & 31;
    const int wm = wid & 1, wn = wid >> 1;

    const __half *pA, *pB;
    int bm, bn;
    bool kvmode;
    if (bid < 512) {
        kvmode = true;
        bm = (bid >> 4) * 128; bn = (bid & 15) * 128;
        pA = gb_ch; pB = gb_wkvh;
    } else {
        kvmode = false;
        int q = bid - 512;
        bm = (q >> 3) * 128; bn = (q & 7) * 128;
        pA = gb_xh; pB = gb_wqh;
    }

    float acc[4][4][4];
#pragma unroll
    for (int i = 0; i < 4; i++)
#pragma unroll
        for (int j = 0; j < 4; j++)
#pragma unroll
            for (int k = 0; k < 4; k++) acc[i][j][k] = 0.f;

    gemm_mainloop2(sb, tid, pA + (size_t)bm * GK, pB + (size_t)bn * GK, acc);

    const int er = lane >> 2;
    const int ec = (lane & 3) * 2;
#pragma unroll
    for (int mt = 0; mt < 4; mt++) {
        int row0 = bm + wm * 64 + mt * 16 + er;
#pragma unroll
        for (int nt = 0; nt < 4; nt++) {
            int col = bn + wn * 32 + nt * 8 + ec;
            float b0 = 0.f, b1 = 0.f;
            if (kvmode) { b0 = b_kv[col]; b1 = b_kv[col + 1]; }
            float v00 = acc[mt][nt][0] + b0, v01 = acc[mt][nt][1] + b1;
            float v10 = acc[mt][nt][2] + b0, v11 = acc[mt][nt][3] + b1;
            if (!kvmode) {
#pragma unroll
                for (int rr = 0; rr < 2; rr++) {
                    int row = row0 + rr * 8;
                    int b_ = row >> 10, n_ = row & 1023;
                    int h_ = col >> 6, d_ = col & 63;
                    size_t idx = ((size_t)(b_ * NH + h_) * NQ + n_) * HD + d_;
                    store_h2(g_qh, idx, rr ? v10 : v00, rr ? v11 : v01);
                }
            } else {
                int kv = col >> 10;
                int h_ = (col >> 6) & 15, d_ = col & 63;
#pragma unroll
                for (int rr = 0; rr < 2; rr++) {
                    int row = row0 + rr * 8;
                    int b_ = row >> 11, m_ = row & 2047;
                    size_t idx = ((size_t)(b_ * NH + h_) * MKV + m_) * HD + d_;
                    if (kv == 0) store_h2(g_kh, idx, rr ? v10 : v00, rr ? v11 : v01);
                    else         store_h2(g_vh, idx, rr ? v10 : v00, rr ? v11 : v01);
                }
            }
        }
    }
}

// ---------------------------------------------------------------------------
// Output projection (512 threads, pure fp16)
// ---------------------------------------------------------------------------
__global__ __launch_bounds__(512, 1) void out_tc(float* __restrict__ C)
{
    extern __shared__ char smem[];
    const uint32_t sb = smem_u32(smem);
    const int tid = threadIdx.x;
    const int wid = tid >> 5, lane = tid & 31;
    const int wm = wid & 3, wn = wid >> 2;
    const int bm = blockIdx.y * 128;
    const int bn = blockIdx.x * 128;

    float acc[2][4][4];
#pragma unroll
    for (int i = 0; i < 2; i++)
#pragma unroll
        for (int j = 0; j < 4; j++)
#pragma unroll
            for (int k = 0; k < 4; k++) acc[i][j][k] = 0.f;

    gemm_mainloop4(sb, tid,
                   gb_aoh + (size_t)bm * GK, gb_woh + (size_t)bn * GK, acc);

    const int er = lane >> 2;
    const int ec = (lane & 3) * 2;
#pragma unroll
    for (int mt = 0; mt < 2; mt++) {
        int row0 = bm + wm * 32 + mt * 16 + er;
#pragma unroll
        for (int nt = 0; nt < 4; nt++) {
            int col = bn + wn * 32 + nt * 8 + ec;
            *(float2*)(C + (size_t)row0 * DIMC + col) =
                make_float2(acc[mt][nt][0], acc[mt][nt][1]);
            *(float2*)(C + (size_t)(row0 + 8) * DIMC + col) =
                make_float2(acc[mt][nt][2], acc[mt][nt][3]);
        }
    }
}

// ---------------------------------------------------------------------------
// Flash attention: pure fp16, fixed softmax reference, l via ones-column MMA.
// The V-tile row pad (bytes 128..143, untouched by cp.async) holds a ones
// column at d=64; one extra n8 MMA per ks accumulates row sums of P exactly.
// ---------------------------------------------------------------------------
#define AT_ROWB 144
#define AT_QTILE (128 * AT_ROWB)
#define AT_KTILE (64 * AT_ROWB)
#define AT_STAGE (2 * AT_KTILE + 1024)
#define AT_NSTG 6
#define AT_SMEM (AT_QTILE + AT_NSTG * AT_STAGE)  // 135168

__global__ __launch_bounds__(512) void attn_tc()
{
    extern __shared__ char smem[];
    const uint32_t sb = smem_u32(smem);
    const int tid = threadIdx.x, wid = tid >> 5, lane = tid & 31;
    const int wg = wid >> 3;
    const int wq = wid & 7;
    const int h = blockIdx.y, b = blockIdx.z;
    const int n0 = blockIdx.x * 128;
    const size_t qbase = ((size_t)(b * NH + h) * NQ + n0) * HD;
    const size_t kvbase = (size_t)(b * NH + h) * MKV * HD;
    const unsigned int* mwbase = g_mw + ((size_t)b * NQ + n0) * 64;

    for (int i = tid; i < 1024; i += 512) {
        int r = i >> 3, c = i & 7;
        CP_ASYNC16(sb + r * AT_ROWB + c * 16,
                   g_qh + qbase + (size_t)r * HD + c * 8);
    }
    CP_COMMIT();

    // initialize ones-column pad in all V-tile slots (cp.async never writes pad)
    for (int i = tid; i < AT_NSTG * 64; i += 512) {
        int slot = i >> 6, r = i & 63;
        uint4* p = (uint4*)(smem + AT_QTILE + (size_t)slot * AT_STAGE
                            + AT_KTILE + r * AT_ROWB + 128);
        *p = make_uint4(0x00003C00u, 0u, 0u, 0u);  // half {1,0}, {0,0}...
    }

    auto load_tile = [&](int t) {
        const uint32_t base = sb + AT_QTILE + (t % AT_NSTG) * AT_STAGE;
        const int m0 = t * 64;
        for (int i = tid; i < 1024; i += 512) {
            int mt = i >> 9, r = (i >> 3) & 63, c = i & 7;
            const __half* p = (mt == 0 ? g_kh : g_vh)
                              + kvbase + (size_t)(m0 + r) * HD + c * 8;
            CP_ASYNC16(base + mt * AT_KTILE + r * AT_ROWB + c * 16, p);
        }
        if (tid < 128)
            CP_ASYNC8(base + 2 * AT_KTILE + tid * 8,
                      mwbase + (size_t)tid * 64 + 2 * t);
        CP_COMMIT();
    };

    load_tile(0); load_tile(1); load_tile(2); load_tile(3);
    CP_WAIT4();
    __syncthreads();

    uint32_t qf[4][4];
    const int wrow = wq * 16;
    {
        const int lr = wrow + ((lane >> 3) & 1) * 8 + (lane & 7);
#pragma unroll
        for (int ks = 0; ks < 4; ks++) {
            uint32_t off = (uint32_t)lr * AT_ROWB + (ks * 16 + (lane >> 4) * 8) * 2;
            ldsm_x4(qf[ks], sb + off);
        }
    }

    float o[8][4];
#pragma unroll
    for (int i = 0; i < 8; i++)
#pragma unroll
        for (int j = 0; j < 4; j++) o[i][j] = 0.f;
    float lacc[4] = {0.f, 0.f, 0.f, 0.f};   // ones-column accumulator
    const int er = lane >> 2, ec = (lane & 3) * 2;

    const int krow = ((lane >> 4) & 1) * 8 + (lane & 7);
    const int kcol = ((lane >> 3) & 1) * 8;
    const int vrow = ((lane >> 3) & 1) * 8 + (lane & 7);
    const int vcol = (lane >> 4) * 8;

    for (int p = 0; p < 16; p++) {
        if (p == 15) CP_WAIT0(); else CP_WAIT2();
        __syncthreads();
        const int t = 2 * p + wg;
        const int slot = t % AT_NSTG;
        const uint32_t stg = sb + AT_QTILE + slot * AT_STAGE;

        // ---- S = Q K^T ----
        float s[8][4];
#pragma unroll
        for (int i = 0; i < 8; i++)
#pragma unroll
            for (int j = 0; j < 4; j++) s[i][j] = 0.f;

#pragma unroll
        for (int ks = 0; ks < 4; ks++) {
            uint32_t bh[4][4];
#pragma unroll
            for (int jm = 0; jm < 4; jm++) {
                uint32_t off = (uint32_t)(jm * 16 + krow) * AT_ROWB + (ks * 16 + kcol) * 2;
                ldsm_x4(bh[jm], stg + off);
            }
#pragma unroll
            for (int jm = 0; jm < 4; jm++) {
                mma_f16(s[2 * jm],     qf[ks], bh[jm]);
                mma_f16(s[2 * jm + 1], qf[ks], bh[jm] + 2);
            }
        }

        // ---- mask + fixed-reference exp ----
        {
            const uint2* mw = (const uint2*)(smem + AT_QTILE
                              + (size_t)slot * AT_STAGE + 2 * AT_KTILE);
            uint2 w0 = mw[wrow + er];
            uint2 w1 = mw[wrow + er + 8];
#pragma unroll
            for (int nt = 0; nt < 8; nt++) {
                int idx = nt * 8 + ec;
                uint32_t wa = (idx & 32) ? w0.y : w0.x;
                uint32_t wb = (idx & 32) ? w1.y : w1.x;
                int sh = idx & 31;
                s[nt][0] = ((wa >> sh) & 1u)       ? s[nt][0] * SC2 : -1e30f;
                s[nt][1] = ((wa >> (sh + 1)) & 1u) ? s[nt][1] * SC2 : -1e30f;
                s[nt][2] = ((wb >> sh) & 1u)       ? s[nt][2] * SC2 : -1e30f;
                s[nt][3] = ((wb >> (sh + 1)) & 1u) ? s[nt][3] * SC2 : -1e30f;
            }
        }

        uint32_t pfrag[4][4];
#pragma unroll
        for (int nt = 0; nt < 8; nt++) {
            uint32_t pk01 = exp2pk(s[nt][0], s[nt][1]);
            uint32_t pk23 = exp2pk(s[nt][2], s[nt][3]);
            int ks = nt >> 1, hi = (nt & 1) * 2;
            pfrag[ks][hi]     = pk01;
            pfrag[ks][hi + 1] = pk23;
        }

        // ---- O += P V ; l += P @ ones (pad column at d=64) ----
#pragma unroll
        for (int ks = 0; ks < 4; ks++) {
            uint32_t bv[4][4];
#pragma unroll
            for (int jd = 0; jd < 4; jd++) {
                uint32_t off = (uint32_t)(ks * 16 + vrow) * AT_ROWB + (jd * 16 + vcol) * 2;
                ldsm_x4_t(bv[jd], stg + AT_KTILE + off);
            }
            uint32_t bw[4];
            {
                uint32_t off = (uint32_t)(ks * 16 + vrow) * AT_ROWB + (64 + vcol) * 2;
                ldsm_x4_t(bw, stg + AT_KTILE + off);
            }
#pragma unroll
            for (int jd = 0; jd < 4; jd++) {
                mma_f16(o[2 * jd],     pfrag[ks], bv[jd]);
                mma_f16(o[2 * jd + 1], pfrag[ks], bv[jd] + 2);
            }
            mma_f16(lacc, pfrag[ks], bw);
        }

        if (p < 14) { load_tile(2 * p + 4); load_tile(2 * p + 5); }
    }

    // lacc col 64 (the row sum) lives in the ec==0 lane of each quad
    float l0r = __shfl_sync(0xffffffffu, lacc[0], lane & 28);
    float l1r = __shfl_sync(0xffffffffu, lacc[2], lane & 28);

    // ---- split-K merge: plain sums ----
    __syncthreads();
    float* mo = (float*)smem;
    float* ml = (float*)(smem + 8 * 16 * 68 * 4);
    if (wg == 1) {
        float* basep = mo + wq * 16 * 68;
#pragma unroll
        for (int nt = 0; nt < 8; nt++) {
            basep[er * 68 + nt * 8 + ec]           = o[nt][0];
            basep[er * 68 + nt * 8 + ec + 1]       = o[nt][1];
            basep[(er + 8) * 68 + nt * 8 + ec]     = o[nt][2];
            basep[(er + 8) * 68 + nt * 8 + ec + 1] = o[nt][3];
        }
        if ((lane & 3) == 0) {
            ml[(wq * 16 + er) * 2]     = l0r;
            ml[(wq * 16 + er + 8) * 2] = l1r;
        }
    }
    __syncthreads();
    if (wg == 0) {
        float inv0 = 1.f / (l0r + ml[(wq * 16 + er) * 2]);
        float inv1 = 1.f / (l1r + ml[(wq * 16 + er + 8) * 2]);
        float* basep = mo + wq * 16 * 68;
#pragma unroll
        for (int nt = 0; nt < 8; nt++) {
            int col = h * HD + nt * 8 + ec;
            float v0 = (o[nt][0] + basep[er * 68 + nt * 8 + ec])           * inv0;
            float v1 = (o[nt][1] + basep[er * 68 + nt * 8 + ec + 1])       * inv0;
            float v2 = (o[nt][2] + basep[(er + 8) * 68 + nt * 8 + ec])     * inv1;
            float v3 = (o[nt][3] + basep[(er + 8) * 68 + nt * 8 + ec + 1]) * inv1;
            size_t i0 = ((size_t)b * NQ + n0 + wrow + er) * DIMC + col;
            size_t i1 = ((size_t)b * NQ + n0 + wrow + er + 8) * DIMC + col;
            store_h2(gb_aoh, i0, v0, v1);
            store_h2(gb_aoh, i1, v2, v3);
        }
    }
}

// ---------------------------------------------------------------------------
// Launch
// ---------------------------------------------------------------------------
extern "C" void kernel_launch(void* const* d_in, const int* in_sizes, int n_in,
                              void* d_out, int out_size)
{
    const float* x        = (const float*)d_in[0];
    const float* context  = (const float*)d_in[1];
    const unsigned int* mask = (const unsigned int*)d_in[2];
    const float* Wq       = (const float*)d_in[3];
    const float* Wkv      = (const float*)d_in[4];
    const float* b_kv     = (const float*)d_in[5];
    const float* Wo       = (const float*)d_in[6];
    float* out            = (float*)d_out;

    cudaFuncSetAttribute(proj_tc, cudaFuncAttributeMaxDynamicSharedMemorySize, GEMM2_SMEM);
    cudaFuncSetAttribute(out_tc, cudaFuncAttributeMaxDynamicSharedMemorySize, GEMM4_SMEM);
    cudaFuncSetAttribute(attn_tc, cudaFuncAttributeMaxDynamicSharedMemorySize, AT_SMEM);

    prep_k<<<NCONVQ / 256, 256>>>(x, context, Wq, Wkv, Wo);
    proj_tc<<<PROJ_GRID, 256, GEMM2_SMEM>>>(b_kv, mask);
    attn_tc<<<dim3(NQ / 128, NH, BATCH), 512, AT_SMEM>>>();
    out_tc<<<dim3(DIMC / 128, (BATCH * NQ) / 128), 512, GEMM4_SMEM>>>(out);
}

// round 17
// speedup vs baseline: 1.0739x; 1.0739x over previous
#include <cuda_runtime.h>
#include <cuda_bf16.h>
#include <cuda_fp16.h>
#include <math.h>
#include <stdint.h>

#define DIMC 1024
#define HD 64
#define NH 16
#define BATCH 2
#define NQ 1024
#define MKV 2048
#define ATT_SCALE 0.125f
#define SC2 0.18033688f   // ATT_SCALE * log2(e)

// ---------------------------------------------------------------------------
// Scratch (pure fp16)
// ---------------------------------------------------------------------------
__device__ __align__(16) __half gb_xh[(size_t)BATCH * NQ * DIMC];
__device__ __align__(16) __half gb_ch[(size_t)BATCH * MKV * DIMC];
__device__ __align__(16) __half gb_wqh[(size_t)DIMC * DIMC];
__device__ __align__(16) __half gb_wkvh[(size_t)2 * DIMC * DIMC];
__device__ __align__(16) __half gb_woh[(size_t)DIMC * DIMC];
__device__ __align__(16) __half gb_aoh[(size_t)BATCH * NQ * DIMC];
__device__ __align__(16) __half g_qh[(size_t)BATCH * NH * NQ * HD];
__device__ __align__(16) __half g_kh[(size_t)BATCH * NH * MKV * HD];
__device__ __align__(16) __half g_vh[(size_t)BATCH * NH * MKV * HD];
__device__ __align__(16) unsigned int g_mw[(size_t)BATCH * NQ * MKV / 32];

// ---------------------------------------------------------------------------
// PTX helpers
// ---------------------------------------------------------------------------
__device__ __forceinline__ uint32_t smem_u32(const void* p) {
    uint32_t a;
    asm("{ .reg .u64 t; cvta.to.shared.u64 t, %1; cvt.u32.u64 %0, t; }"
        : "=r"(a) : "l"(p));
    return a;
}

#define CP_ASYNC16(dst, src) \
    asm volatile("cp.async.cg.shared.global [%0], [%1], 16;" \
                 :: "r"(dst), "l"(src) : "memory")
#define CP_ASYNC8(dst, src) \
    asm volatile("cp.async.ca.shared.global [%0], [%1], 8;" \
                 :: "r"(dst), "l"(src) : "memory")
#define CP_COMMIT() asm volatile("cp.async.commit_group;" ::: "memory")
#define CP_WAIT4()  asm volatile("cp.async.wait_group 4;" ::: "memory")
#define CP_WAIT2()  asm volatile("cp.async.wait_group 2;" ::: "memory")
#define CP_WAIT1()  asm volatile("cp.async.wait_group 1;" ::: "memory")
#define CP_WAIT0()  asm volatile("cp.async.wait_group 0;" ::: "memory")

__device__ __forceinline__ void ldsm_x4(uint32_t* r, uint32_t addr) {
    asm volatile("ldmatrix.sync.aligned.m8n8.x4.shared.b16 {%0,%1,%2,%3}, [%4];"
                 : "=r"(r[0]), "=r"(r[1]), "=r"(r[2]), "=r"(r[3]) : "r"(addr));
}
__device__ __forceinline__ void ldsm_x4_t(uint32_t* r, uint32_t addr) {
    asm volatile("ldmatrix.sync.aligned.m8n8.x4.trans.shared.b16 {%0,%1,%2,%3}, [%4];"
                 : "=r"(r[0]), "=r"(r[1]), "=r"(r[2]), "=r"(r[3]) : "r"(addr));
}
__device__ __forceinline__ void mma_f16(float* c, const uint32_t* a, const uint32_t* b) {
    asm volatile(
        "mma.sync.aligned.m16n8k16.row.col.f32.f16.f16.f32 "
        "{%0,%1,%2,%3}, {%4,%5,%6,%7}, {%8,%9}, {%0,%1,%2,%3};"
        : "+f"(c[0]), "+f"(c[1]), "+f"(c[2]), "+f"(c[3])
        : "r"(a[0]), "r"(a[1]), "r"(a[2]), "r"(a[3]), "r"(b[0]), "r"(b[1]));
}

__device__ __forceinline__ uint32_t exp2pk(float a, float b) {
    uint32_t h;
    asm("cvt.rn.f16x2.f32 %0, %1, %2;" : "=r"(h) : "f"(b), "f"(a));
    asm("ex2.approx.f16x2 %0, %0;" : "+r"(h));
    return h;
}
__device__ __forceinline__ float2 h2f(uint32_t h) {
    __half2 v = *reinterpret_cast<__half2*>(&h);
    return make_float2(__half2float(v.x), __half2float(v.y));
}
__device__ __forceinline__ void store_h2(__half* H, size_t idx, float v0, float v1) {
    *(__half2*)(H + idx) = __halves2half2(__float2half_rn(v0), __float2half_rn(v1));
}

// ---------------------------------------------------------------------------
// Fused prep: fp32 -> fp16 convert (x, ctx, Wq, Wkv, Wo) + mask bits
// ---------------------------------------------------------------------------
#define NXQ ((BATCH * NQ * DIMC) / 4)
#define NCTXQ ((BATCH * MKV * DIMC) / 4)
#define NWQQ ((DIMC * DIMC) / 4)
#define NWKVQ ((2 * DIMC * DIMC) / 4)
#define NWOQ ((DIMC * DIMC) / 4)
#define NCONVQ (NXQ + NCTXQ + NWQQ + NWKVQ + NWOQ)
#define NMASKE (BATCH * NQ * MKV)
#define PREP_TOTAL (NCONVQ + NMASKE)

__global__ void prep_k(const float* __restrict__ x, const float* __restrict__ ctx,
                       const float* __restrict__ Wq, const float* __restrict__ Wkv,
                       const float* __restrict__ Wo, const unsigned int* __restrict__ mask)
{
    int i = blockIdx.x * blockDim.x + threadIdx.x;
    const int q0 = NXQ, q1 = q0 + NCTXQ, q2 = q1 + NWQQ, q3 = q2 + NWKVQ, q4 = q3 + NWOQ;

    if (i < q4) {
        const float* src; __half* H; int off = i;
        if (i < q0)      { src = x;   H = gb_xh; }
        else if (i < q1) { src = ctx; H = gb_ch;   off -= q0; }
        else if (i < q2) { src = Wq;  H = gb_wqh;  off -= q1; }
        else if (i < q3) { src = Wkv; H = gb_wkvh; off -= q2; }
        else             { src = Wo;  H = gb_woh;  off -= q3; }
        float4 v = ((const float4*)src)[off];
        __half2 hp0 = __halves2half2(__float2half_rn(v.x), __float2half_rn(v.y));
        __half2 hp1 = __halves2half2(__float2half_rn(v.z), __float2half_rn(v.w));
        uint2 hp;
        hp.x = *(uint32_t*)&hp0; hp.y = *(uint32_t*)&hp1;
        ((uint2*)H)[off] = hp;
    } else if (i < PREP_TOTAL) {
        int j = i - q4;
        unsigned int v = mask[j];
        unsigned int bits = __ballot_sync(0xffffffffu, v != 0u);
        if ((threadIdx.x & 31) == 0) g_mw[j >> 5] = bits;
    }
}

// ---------------------------------------------------------------------------
// Shared GEMM tile constants: BK=64, 3-stage, one barrier per K-slab.
// ---------------------------------------------------------------------------
#define BK 64
#define GK 1024
#define GNT (GK / BK)       // 16
#define ROWB 144            // 128B data + 16B pad
#define TILEB (128 * ROWB)  // 18432

// ============ proj mainloop: 256 threads, 3-stage, 1-term ==================
#define PROJ_STAGEB (2 * TILEB)       // 36864
#define GEMM2_SMEM (3 * PROJ_STAGEB)  // 110592

__device__ __forceinline__ void gemm_mainloop2(
    uint32_t sb, int tid,
    const __half* __restrict__ A, const __half* __restrict__ B,
    float acc[4][4][4])
{
    const int wid = tid >> 5, lane = tid & 31;
    const int wm = wid & 1;
    const int wn = wid >> 1;
    const __half* srcs[2] = { A, B };

    auto load_stage = [&](int t, int stage) {
        const uint32_t base = sb + stage * PROJ_STAGEB;
#pragma unroll
        for (int m = 0; m < 2; m++) {
            const __half* src = srcs[m] + (size_t)t * BK;
#pragma unroll
            for (int rep = 0; rep < 4; rep++) {
                int f = tid + rep * 256;
                int row = f >> 3;
                int ch = f & 7;
                CP_ASYNC16(base + m * TILEB + row * ROWB + ch * 16,
                           src + (size_t)row * GK + ch * 8);
            }
        }
        CP_COMMIT();
    };

    load_stage(0, 0);
    load_stage(1, 1);

    const int a_row = wm * 64 + (lane & 7) + 8 * ((lane >> 3) & 1);
    const int a_kof = 8 * (lane >> 4);
    const int b_row = wn * 32 + (lane & 7) + 8 * (lane >> 4);
    const int b_kof = 8 * ((lane >> 3) & 1);

    for (int t = 0; t < GNT; t++) {
        if (t + 1 < GNT) CP_WAIT1(); else CP_WAIT0();
        __syncthreads();
        if (t + 2 < GNT) load_stage(t + 2, (t + 2) % 3);

        const uint32_t sA = sb + (t % 3) * PROJ_STAGEB;
        const uint32_t sB = sA + TILEB;

#pragma unroll
        for (int kk = 0; kk < BK; kk += 16) {
            uint32_t a_f[4][4];
#pragma unroll
            for (int mt = 0; mt < 4; mt++) {
                uint32_t off = (uint32_t)(a_row + mt * 16) * ROWB + (kk + a_kof) * 2;
                ldsm_x4(a_f[mt], sA + off);
            }
            uint32_t b_f[8];
#pragma unroll
            for (int np = 0; np < 2; np++) {
                uint32_t off = (uint32_t)(b_row + np * 16) * ROWB + (kk + b_kof) * 2;
                ldsm_x4(b_f + np * 4, sB + off);
            }
#pragma unroll
            for (int mt = 0; mt < 4; mt++)
#pragma unroll
                for (int nt = 0; nt < 4; nt++)
                    mma_f16(acc[mt][nt], a_f[mt], b_f + nt * 2);
        }
    }
}

// ============ out mainloop: 512 threads, 3-stage, 1-term ===================
#define OUT_STAGEB (2 * TILEB)
#define GEMM4_SMEM (3 * OUT_STAGEB)

__device__ __forceinline__ void gemm_mainloop4(
    uint32_t sb, int tid,
    const __half* __restrict__ A, const __half* __restrict__ B,
    float acc[2][4][4])
{
    const int wid = tid >> 5, lane = tid & 31;
    const int wm = wid & 3;
    const int wn = wid >> 2;
    const __half* srcs[2] = { A, B };

    auto load_stage = [&](int t, int stage) {
        const uint32_t base = sb + stage * OUT_STAGEB;
#pragma unroll
        for (int m = 0; m < 2; m++) {
            const __half* src = srcs[m] + (size_t)t * BK;
#pragma unroll
            for (int rep = 0; rep < 2; rep++) {
                int f = tid + rep * 512;
                int row = f >> 3;
                int ch = f & 7;
                CP_ASYNC16(base + m * TILEB + row * ROWB + ch * 16,
                           src + (size_t)row * GK + ch * 8);
            }
        }
        CP_COMMIT();
    };

    load_stage(0, 0);
    load_stage(1, 1);

    const int a_rowb = wm * 32 + (lane & 7) + 8 * ((lane >> 3) & 1);
    const int a_kof = 8 * (lane >> 4);
    const int b_rowb = wn * 32 + (lane & 7) + 8 * (lane >> 4);
    const int b_kof = 8 * ((lane >> 3) & 1);

    for (int t = 0; t < GNT; t++) {
        if (t + 1 < GNT) CP_WAIT1(); else CP_WAIT0();
        __syncthreads();
        if (t + 2 < GNT) load_stage(t + 2, (t + 2) % 3);

        const uint32_t sA = sb + (t % 3) * OUT_STAGEB;
        const uint32_t sB = sA + TILEB;

#pragma unroll
        for (int kk = 0; kk < BK; kk += 16) {
            uint32_t a_f[2][4];
#pragma unroll
            for (int mt = 0; mt < 2; mt++) {
                uint32_t off = (uint32_t)(a_rowb + mt * 16) * ROWB + (kk + a_kof) * 2;
                ldsm_x4(a_f[mt], sA + off);
            }
            uint32_t b_f[8];
#pragma unroll
            for (int np = 0; np < 2; np++) {
                uint32_t off = (uint32_t)(b_rowb + np * 16) * ROWB + (kk + b_kof) * 2;
                ldsm_x4(b_f + np * 4, sB + off);
            }
#pragma unroll
            for (int mt = 0; mt < 2; mt++)
#pragma unroll
                for (int nt = 0; nt < 4; nt++)
                    mma_f16(acc[mt][nt], a_f[mt], b_f + nt * 2);
        }
    }
}

// ---------------------------------------------------------------------------
// Merged Q + KV projection (256 threads, pure fp16)
// ---------------------------------------------------------------------------
__global__ __launch_bounds__(256, 2) void proj_tc(const float* __restrict__ b_kv)
{
    extern __shared__ char smem[];
    const uint32_t sb = smem_u32(smem);
    const int tid = threadIdx.x;
    const int wid = tid >> 5, lane = tid & 31;
    const int wm = wid & 1, wn = wid >> 1;
    const int bid = blockIdx.x;

    const __half *pA, *pB;
    int bm, bn;
    bool kvmode;
    if (bid < 512) {
        kvmode = true;
        bm = (bid >> 4) * 128; bn = (bid & 15) * 128;
        pA = gb_ch; pB = gb_wkvh;
    } else {
        kvmode = false;
        int q = bid - 512;
        bm = (q >> 3) * 128; bn = (q & 7) * 128;
        pA = gb_xh; pB = gb_wqh;
    }

    float acc[4][4][4];
#pragma unroll
    for (int i = 0; i < 4; i++)
#pragma unroll
        for (int j = 0; j < 4; j++)
#pragma unroll
            for (int k = 0; k < 4; k++) acc[i][j][k] = 0.f;

    gemm_mainloop2(sb, tid, pA + (size_t)bm * GK, pB + (size_t)bn * GK, acc);

    const int er = lane >> 2;
    const int ec = (lane & 3) * 2;
#pragma unroll
    for (int mt = 0; mt < 4; mt++) {
        int row0 = bm + wm * 64 + mt * 16 + er;
#pragma unroll
        for (int nt = 0; nt < 4; nt++) {
            int col = bn + wn * 32 + nt * 8 + ec;
            float b0 = 0.f, b1 = 0.f;
            if (kvmode) { b0 = b_kv[col]; b1 = b_kv[col + 1]; }
            float v00 = acc[mt][nt][0] + b0, v01 = acc[mt][nt][1] + b1;
            float v10 = acc[mt][nt][2] + b0, v11 = acc[mt][nt][3] + b1;
            if (!kvmode) {
#pragma unroll
                for (int rr = 0; rr < 2; rr++) {
                    int row = row0 + rr * 8;
                    int b_ = row >> 10, n_ = row & 1023;
                    int h_ = col >> 6, d_ = col & 63;
                    size_t idx = ((size_t)(b_ * NH + h_) * NQ + n_) * HD + d_;
                    store_h2(g_qh, idx, rr ? v10 : v00, rr ? v11 : v01);
                }
            } else {
                int kv = col >> 10;
                int h_ = (col >> 6) & 15, d_ = col & 63;
#pragma unroll
                for (int rr = 0; rr < 2; rr++) {
                    int row = row0 + rr * 8;
                    int b_ = row >> 11, m_ = row & 2047;
                    size_t idx = ((size_t)(b_ * NH + h_) * MKV + m_) * HD + d_;
                    if (kv == 0) store_h2(g_kh, idx, rr ? v10 : v00, rr ? v11 : v01);
                    else         store_h2(g_vh, idx, rr ? v10 : v00, rr ? v11 : v01);
                }
            }
        }
    }
}

// ---------------------------------------------------------------------------
// Output projection (512 threads, pure fp16)
// ---------------------------------------------------------------------------
__global__ __launch_bounds__(512, 1) void out_tc(float* __restrict__ C)
{
    extern __shared__ char smem[];
    const uint32_t sb = smem_u32(smem);
    const int tid = threadIdx.x;
    const int wid = tid >> 5, lane = tid & 31;
    const int wm = wid & 3, wn = wid >> 2;
    const int bm = blockIdx.y * 128;
    const int bn = blockIdx.x * 128;

    float acc[2][4][4];
#pragma unroll
    for (int i = 0; i < 2; i++)
#pragma unroll
        for (int j = 0; j < 4; j++)
#pragma unroll
            for (int k = 0; k < 4; k++) acc[i][j][k] = 0.f;

    gemm_mainloop4(sb, tid,
                   gb_aoh + (size_t)bm * GK, gb_woh + (size_t)bn * GK, acc);

    const int er = lane >> 2;
    const int ec = (lane & 3) * 2;
#pragma unroll
    for (int mt = 0; mt < 2; mt++) {
        int row0 = bm + wm * 32 + mt * 16 + er;
#pragma unroll
        for (int nt = 0; nt < 4; nt++) {
            int col = bn + wn * 32 + nt * 8 + ec;
            *(float2*)(C + (size_t)row0 * DIMC + col) =
                make_float2(acc[mt][nt][0], acc[mt][nt][1]);
            *(float2*)(C + (size_t)(row0 + 8) * DIMC + col) =
                make_float2(acc[mt][nt][2], acc[mt][nt][3]);
        }
    }
}

// ---------------------------------------------------------------------------
// Flash attention: pure fp16, fixed softmax reference (m == 0):
// 512 threads, warp split-K, mask bits, 6-stage, 1 barrier/iter.
// ---------------------------------------------------------------------------
#define AT_ROWB 144
#define AT_QTILE (128 * AT_ROWB)
#define AT_KTILE (64 * AT_ROWB)
#define AT_STAGE (2 * AT_KTILE + 1024)
#define AT_NSTG 6
#define AT_SMEM (AT_QTILE + AT_NSTG * AT_STAGE)  // 135168

__global__ __launch_bounds__(512) void attn_tc()
{
    extern __shared__ char smem[];
    const uint32_t sb = smem_u32(smem);
    const int tid = threadIdx.x, wid = tid >> 5, lane = tid & 31;
    const int wg = wid >> 3;
    const int wq = wid & 7;
    const int h = blockIdx.y, b = blockIdx.z;
    const int n0 = blockIdx.x * 128;
    const size_t qbase = ((size_t)(b * NH + h) * NQ + n0) * HD;
    const size_t kvbase = (size_t)(b * NH + h) * MKV * HD;
    const unsigned int* mwbase = g_mw + ((size_t)b * NQ + n0) * 64;

    for (int i = tid; i < 1024; i += 512) {
        int r = i >> 3, c = i & 7;
        CP_ASYNC16(sb + r * AT_ROWB + c * 16,
                   g_qh + qbase + (size_t)r * HD + c * 8);
    }
    CP_COMMIT();

    auto load_tile = [&](int t) {
        const uint32_t base = sb + AT_QTILE + (t % AT_NSTG) * AT_STAGE;
        const int m0 = t * 64;
        for (int i = tid; i < 1024; i += 512) {
            int mt = i >> 9, r = (i >> 3) & 63, c = i & 7;
            const __half* p = (mt == 0 ? g_kh : g_vh)
                              + kvbase + (size_t)(m0 + r) * HD + c * 8;
            CP_ASYNC16(base + mt * AT_KTILE + r * AT_ROWB + c * 16, p);
        }
        if (tid < 128)
            CP_ASYNC8(base + 2 * AT_KTILE + tid * 8,
                      mwbase + (size_t)tid * 64 + 2 * t);
        CP_COMMIT();
    };

    load_tile(0); load_tile(1); load_tile(2); load_tile(3);
    CP_WAIT4();
    __syncthreads();

    uint32_t qf[4][4];
    const int wrow = wq * 16;
    {
        const int lr = wrow + ((lane >> 3) & 1) * 8 + (lane & 7);
#pragma unroll
        for (int ks = 0; ks < 4; ks++) {
            uint32_t off = (uint32_t)lr * AT_ROWB + (ks * 16 + (lane >> 4) * 8) * 2;
            ldsm_x4(qf[ks], sb + off);
        }
    }

    float o[8][4];
#pragma unroll
    for (int i = 0; i < 8; i++)
#pragma unroll
        for (int j = 0; j < 4; j++) o[i][j] = 0.f;
    float l0r = 0.f, l1r = 0.f;
    const int er = lane >> 2, ec = (lane & 3) * 2;

    const int krow = ((lane >> 4) & 1) * 8 + (lane & 7);
    const int kcol = ((lane >> 3) & 1) * 8;

    for (int p = 0; p < 16; p++) {
        if (p == 15) CP_WAIT0(); else CP_WAIT2();
        __syncthreads();
        const int t = 2 * p + wg;
        const int slot = t % AT_NSTG;
        const uint32_t stg = sb + AT_QTILE + slot * AT_STAGE;

        // ---- S = Q K^T ----
        float s[8][4];
#pragma unroll
        for (int i = 0; i < 8; i++)
#pragma unroll
            for (int j = 0; j < 4; j++) s[i][j] = 0.f;

#pragma unroll
        for (int ks = 0; ks < 4; ks++) {
            uint32_t bh[4][4];
#pragma unroll
            for (int jm = 0; jm < 4; jm++) {
                uint32_t off = (uint32_t)(jm * 16 + krow) * AT_ROWB + (ks * 16 + kcol) * 2;
                ldsm_x4(bh[jm], stg + off);
            }
#pragma unroll
            for (int jm = 0; jm < 4; jm++) {
                mma_f16(s[2 * jm],     qf[ks], bh[jm]);
                mma_f16(s[2 * jm + 1], qf[ks], bh[jm] + 2);
            }
        }

        // ---- mask + fixed-reference exp ----
        {
            const uint2* mw = (const uint2*)(smem + AT_QTILE
                              + (size_t)slot * AT_STAGE + 2 * AT_KTILE);
            uint2 w0 = mw[wrow + er];
            uint2 w1 = mw[wrow + er + 8];
#pragma unroll
            for (int nt = 0; nt < 8; nt++) {
                int idx = nt * 8 + ec;
                uint32_t wa = (idx & 32) ? w0.y : w0.x;
                uint32_t wb = (idx & 32) ? w1.y : w1.x;
                int sh = idx & 31;
                s[nt][0] = ((wa >> sh) & 1u)       ? s[nt][0] * SC2 : -1e30f;
                s[nt][1] = ((wa >> (sh + 1)) & 1u) ? s[nt][1] * SC2 : -1e30f;
                s[nt][2] = ((wb >> sh) & 1u)       ? s[nt][2] * SC2 : -1e30f;
                s[nt][3] = ((wb >> (sh + 1)) & 1u) ? s[nt][3] * SC2 : -1e30f;
            }
        }

        uint32_t pfrag[4][4];
        float sum0 = 0.f, sum1 = 0.f;
#pragma unroll
        for (int nt = 0; nt < 8; nt++) {
            uint32_t pk01 = exp2pk(s[nt][0], s[nt][1]);
            uint32_t pk23 = exp2pk(s[nt][2], s[nt][3]);
            int ks = nt >> 1, hi = (nt & 1) * 2;
            pfrag[ks][hi]     = pk01;
            pfrag[ks][hi + 1] = pk23;
            float2 e01 = h2f(pk01), e23 = h2f(pk23);
            sum0 += e01.x + e01.y;
            sum1 += e23.x + e23.y;
        }
        l0r += sum0;
        l1r += sum1;

        // ---- O += P V ----
#pragma unroll
        for (int ks = 0; ks < 4; ks++) {
            uint32_t bv[4][4];
#pragma unroll
            for (int jd = 0; jd < 4; jd++) {
                uint32_t off = (uint32_t)(ks * 16 + ((lane >> 3) & 1) * 8 + (lane & 7)) * AT_ROWB
                             + (jd * 16 + (lane >> 4) * 8) * 2;
                ldsm_x4_t(bv[jd], stg + AT_KTILE + off);
            }
#pragma unroll
            for (int jd = 0; jd < 4; jd++) {
                mma_f16(o[2 * jd],     pfrag[ks], bv[jd]);
                mma_f16(o[2 * jd + 1], pfrag[ks], bv[jd] + 2);
            }
        }

        if (p < 14) { load_tile(2 * p + 4); load_tile(2 * p + 5); }
    }

    // ---- row-sum reduce within quad ----
    l0r += __shfl_xor_sync(0xffffffffu, l0r, 1);
    l0r += __shfl_xor_sync(0xffffffffu, l0r, 2);
    l1r += __shfl_xor_sync(0xffffffffu, l1r, 1);
    l1r += __shfl_xor_sync(0xffffffffu, l1r, 2);

    // ---- split-K merge: plain sums ----
    __syncthreads();
    float* mo = (float*)smem;
    float* ml = (float*)(smem + 8 * 16 * 68 * 4);
    if (wg == 1) {
        float* basep = mo + wq * 16 * 68;
#pragma unroll
        for (int nt = 0; nt < 8; nt++) {
            basep[er * 68 + nt * 8 + ec]           = o[nt][0];
            basep[er * 68 + nt * 8 + ec + 1]       = o[nt][1];
            basep[(er + 8) * 68 + nt * 8 + ec]     = o[nt][2];
            basep[(er + 8) * 68 + nt * 8 + ec + 1] = o[nt][3];
        }
        if ((lane & 3) == 0) {
            ml[(wq * 16 + er) * 2]     = l0r;
            ml[(wq * 16 + er + 8) * 2] = l1r;
        }
    }
    __syncthreads();
    if (wg == 0) {
        float inv0 = 1.f / (l0r + ml[(wq * 16 + er) * 2]);
        float inv1 = 1.f / (l1r + ml[(wq * 16 + er + 8) * 2]);
        float* basep = mo + wq * 16 * 68;
#pragma unroll
        for (int nt = 0; nt < 8; nt++) {
            int col = h * HD + nt * 8 + ec;
            float v0 = (o[nt][0] + basep[er * 68 + nt * 8 + ec])           * inv0;
            float v1 = (o[nt][1] + basep[er * 68 + nt * 8 + ec + 1])       * inv0;
            float v2 = (o[nt][2] + basep[(er + 8) * 68 + nt * 8 + ec])     * inv1;
            float v3 = (o[nt][3] + basep[(er + 8) * 68 + nt * 8 + ec + 1]) * inv1;
            size_t i0 = ((size_t)b * NQ + n0 + wrow + er) * DIMC + col;
            size_t i1 = ((size_t)b * NQ + n0 + wrow + er + 8) * DIMC + col;
            store_h2(gb_aoh, i0, v0, v1);
            store_h2(gb_aoh, i1, v2, v3);
        }
    }
}

// ---------------------------------------------------------------------------
// Launch
// ---------------------------------------------------------------------------
extern "C" void kernel_launch(void* const* d_in, const int* in_sizes, int n_in,
                              void* d_out, int out_size)
{
    const float* x        = (const float*)d_in[0];
    const float* context  = (const float*)d_in[1];
    const unsigned int* mask = (const unsigned int*)d_in[2];
    const float* Wq       = (const float*)d_in[3];
    const float* Wkv      = (const float*)d_in[4];
    const float* b_kv     = (const float*)d_in[5];
    const float* Wo       = (const float*)d_in[6];
    float* out            = (float*)d_out;

    cudaFuncSetAttribute(proj_tc, cudaFuncAttributeMaxDynamicSharedMemorySize, GEMM2_SMEM);
    cudaFuncSetAttribute(out_tc, cudaFuncAttributeMaxDynamicSharedMemorySize, GEMM4_SMEM);
    cudaFuncSetAttribute(attn_tc, cudaFuncAttributeMaxDynamicSharedMemorySize, AT_SMEM);

    prep_k<<<(PREP_TOTAL + 255) / 256, 256>>>(x, context, Wq, Wkv, Wo, mask);
    proj_tc<<<640, 256, GEMM2_SMEM>>>(b_kv);
    attn_tc<<<dim3(NQ / 128, NH, BATCH), 512, AT_SMEM>>>();
    out_tc<<<dim3(DIMC / 128, (BATCH * NQ) / 128), 512, GEMM4_SMEM>>>(out);
}